// round 7
// baseline (speedup 1.0000x reference)
#include <cuda_runtime.h>
#include <cuda_bf16.h>

// Depthwise conv1d, fixed shape: B=4, D=2048, L=8192, K=3, pad=1 -> L_out=L.
// out[b,d,l] = bias[d] + w[d,0]*x[l-1] + w[d,1]*x[l] + w[d,2]*x[l+1]
//
// Quad-stream one-shot kernel: each thread handles FOUR 8-element tiles
// (2x float4 each) from tensor quarters 64MB apart. 8 independent LDG.128
// front-batched -> per-thread MLP=8 across four DRAM streams; four
// independent FMA/store chains overlap each other's load latency.
// Halos via warp shuffle per stream; only warp-edge lanes touch memory.
// Warp = 256 contiguous elements per stream; quarters are row-aligned
// (16,777,216 / 8192 = 2048 rows), so per-stream l/d masks remain valid.

#define CONV_B 4
#define CONV_D 2048
#define CONV_L 8192
#define EPT 8
#define TOTAL_ELEMS (CONV_B * CONV_D * CONV_L)      // 67,108,864
#define QUARTER     (TOTAL_ELEMS / 4)               // 16,777,216
#define NSTREAMS 4

__global__ __launch_bounds__(256) void dwconv1d_k3_kernel(
    const float* __restrict__ x,     // [B*D, L]
    const float* __restrict__ w,     // [D, 3]
    const float* __restrict__ bias,  // [D]
    float* __restrict__ out)         // [B*D, L]
{
    const unsigned tid  = blockIdx.x * blockDim.x + threadIdx.x;
    const unsigned lane = threadIdx.x & 31;

    unsigned base[NSTREAMS];
    #pragma unroll
    for (int s = 0; s < NSTREAMS; s++)
        base[s] = tid * EPT + s * QUARTER;

    // ---- front-batched payload loads: 8 independent LDG.128 ----
    float4 v0[NSTREAMS], v1[NSTREAMS];
    #pragma unroll
    for (int s = 0; s < NSTREAMS; s++) {
        const float4* xv = reinterpret_cast<const float4*>(x + base[s]);
        v0[s] = xv[0];
        v1[s] = xv[1];
    }

    // ---- weights / bias (uniform across warp per stream) ----
    float w0[NSTREAMS], w1[NSTREAMS], w2[NSTREAMS], bv[NSTREAMS];
    unsigned lpos[NSTREAMS];
    #pragma unroll
    for (int s = 0; s < NSTREAMS; s++) {
        lpos[s] = base[s] & (CONV_L - 1);
        const unsigned d = (base[s] >> 13) & (CONV_D - 1);
        w0[s] = __ldg(&w[d * 3 + 0]);
        w1[s] = __ldg(&w[d * 3 + 1]);
        w2[s] = __ldg(&w[d * 3 + 2]);
        bv[s] = __ldg(&bias[d]);
    }

    // ---- halos via shuffle; warp-edge lanes fall back to memory ----
    float left[NSTREAMS], right[NSTREAMS];
    #pragma unroll
    for (int s = 0; s < NSTREAMS; s++) {
        left[s]  = __shfl_up_sync(0xffffffffu, v1[s].w, 1);
        right[s] = __shfl_down_sync(0xffffffffu, v0[s].x, 1);
    }
    if (lane == 0) {
        #pragma unroll
        for (int s = 0; s < NSTREAMS; s++)
            left[s] = (lpos[s] > 0) ? __ldg(x + base[s] - 1) : 0.0f;
    }
    if (lane == 31) {
        #pragma unroll
        for (int s = 0; s < NSTREAMS; s++)
            right[s] = (lpos[s] + EPT < CONV_L) ? __ldg(x + base[s] + EPT) : 0.0f;
    }

    // ---- 4 independent compute + store chains ----
    #pragma unroll
    for (int s = 0; s < NSTREAMS; s++) {
        const float4 a = v0[s], b = v1[s];
        float4 o0, o1;
        o0.x = fmaf(w0[s], left[s], fmaf(w1[s], a.x, fmaf(w2[s], a.y, bv[s])));
        o0.y = fmaf(w0[s], a.x, fmaf(w1[s], a.y, fmaf(w2[s], a.z, bv[s])));
        o0.z = fmaf(w0[s], a.y, fmaf(w1[s], a.z, fmaf(w2[s], a.w, bv[s])));
        o0.w = fmaf(w0[s], a.z, fmaf(w1[s], a.w, fmaf(w2[s], b.x, bv[s])));
        o1.x = fmaf(w0[s], a.w, fmaf(w1[s], b.x, fmaf(w2[s], b.y, bv[s])));
        o1.y = fmaf(w0[s], b.x, fmaf(w1[s], b.y, fmaf(w2[s], b.z, bv[s])));
        o1.z = fmaf(w0[s], b.y, fmaf(w1[s], b.z, fmaf(w2[s], b.w, bv[s])));
        o1.w = fmaf(w0[s], b.z, fmaf(w1[s], b.w, fmaf(w2[s], right[s], bv[s])));

        float4* ov = reinterpret_cast<float4*>(out + base[s]);
        __stcs(&ov[0], o0);
        __stcs(&ov[1], o1);
    }
}

extern "C" void kernel_launch(void* const* d_in, const int* in_sizes, int n_in,
                              void* d_out, int out_size)
{
    const float* x    = (const float*)d_in[0];
    const float* w    = (const float*)d_in[1];
    const float* bias = (const float*)d_in[2];
    float*       out  = (float*)d_out;

    const int threads = 256;
    const int blocks  = QUARTER / (threads * EPT);   // 8192

    dwconv1d_k3_kernel<<<blocks, threads>>>(x, w, bias, out);
}

// round 9
// speedup vs baseline: 1.0094x; 1.0094x over previous
#include <cuda_runtime.h>
#include <cuda_bf16.h>

// Depthwise conv1d, fixed shape: B=4, D=2048, L=8192, K=3, pad=1 -> L_out=L.
// out[b,d,l] = bias[d] + w[d,0]*x[l-1] + w[d,1]*x[l] + w[d,2]*x[l+1]
//
// Dual-stream, warp-coalesced kernel. A warp owns 256 contiguous elements
// (64 float4) per stream; thread lane handles float4 #lane and #(lane+32),
// so every LDG.128 / STG.128 is a dense 512B warp transaction (no sector
// fragmentation -- previous layout half-filled each 32B sector per store).
// Two streams from tensor halves 128MB apart give per-thread MLP=4 with two
// independent FMA/store chains. All halos via warp shuffle except the two
// warp-edge lanes. Warp tile never straddles a row (256 | 8192).

#define CONV_B 4
#define CONV_D 2048
#define CONV_L 8192
#define TOTAL_ELEMS (CONV_B * CONV_D * CONV_L)      // 67,108,864
#define HALF_ELEMS  (TOTAL_ELEMS / 2)               // 33,554,432 (row-aligned)
#define NSTREAMS 2

__global__ __launch_bounds__(256) void dwconv1d_k3_kernel(
    const float* __restrict__ x,     // [B*D, L]
    const float* __restrict__ w,     // [D, 3]
    const float* __restrict__ bias,  // [D]
    float* __restrict__ out)         // [B*D, L]
{
    const unsigned tid  = blockIdx.x * blockDim.x + threadIdx.x;
    const unsigned lane = threadIdx.x & 31;
    const unsigned warpTile = (tid >> 5) * 256;     // warp-base element, stream 0

    unsigned Wb[NSTREAMS];                          // warp-base per stream
    #pragma unroll
    for (int s = 0; s < NSTREAMS; s++)
        Wb[s] = warpTile + s * HALF_ELEMS;

    // ---- front-batched payload loads: 4 dense LDG.128 (512B/warp each) ----
    float4 va[NSTREAMS], vb[NSTREAMS];
    #pragma unroll
    for (int s = 0; s < NSTREAMS; s++) {
        const float4* xv = reinterpret_cast<const float4*>(x + Wb[s]);
        va[s] = xv[lane];         // chunk A: elements Wb + lane*4 .. +3
        vb[s] = xv[lane + 32];    // chunk B: elements Wb + 128 + lane*4 .. +3
    }

    // ---- weights / bias: uniform across warp per stream ----
    float w0[NSTREAMS], w1[NSTREAMS], w2[NSTREAMS], bv[NSTREAMS];
    #pragma unroll
    for (int s = 0; s < NSTREAMS; s++) {
        const unsigned d = (Wb[s] >> 13) & (CONV_D - 1);
        w0[s] = __ldg(&w[d * 3 + 0]);
        w1[s] = __ldg(&w[d * 3 + 1]);
        w2[s] = __ldg(&w[d * 3 + 2]);
        bv[s] = __ldg(&bias[d]);
    }

    // ---- halo exchange via shuffles ----
    // chunk A of lane i: left = lane i-1's A.w ; right = lane i+1's A.x,
    //   except lane 31's right = lane 0's B.x (element Wb+128)
    // chunk B of lane i: left = lane i-1's B.w,
    //   except lane 0's left = lane 31's A.w (element Wb+127)
    //   right = lane i+1's B.x, except lane 31 -> memory (element Wb+256)
    float lA[NSTREAMS], rA[NSTREAMS], lB[NSTREAMS], rB[NSTREAMS];
    #pragma unroll
    for (int s = 0; s < NSTREAMS; s++) {
        lA[s] = __shfl_up_sync(0xffffffffu, va[s].w, 1);
        rA[s] = __shfl_down_sync(0xffffffffu, va[s].x, 1);
        lB[s] = __shfl_up_sync(0xffffffffu, vb[s].w, 1);
        rB[s] = __shfl_down_sync(0xffffffffu, vb[s].x, 1);
        const float aw31 = __shfl_sync(0xffffffffu, va[s].w, 31);
        const float bx0  = __shfl_sync(0xffffffffu, vb[s].x, 0);
        if (lane == 31) rA[s] = bx0;
        if (lane == 0)  lB[s] = aw31;
    }
    if (lane == 0) {
        #pragma unroll
        for (int s = 0; s < NSTREAMS; s++) {
            const unsigned lpos = Wb[s] & (CONV_L - 1);
            lA[s] = (lpos > 0) ? __ldg(x + Wb[s] - 1) : 0.0f;
        }
    }
    if (lane == 31) {
        #pragma unroll
        for (int s = 0; s < NSTREAMS; s++) {
            const unsigned lend = (Wb[s] + 256) & (CONV_L - 1);
            rB[s] = (lend != 0) ? __ldg(x + Wb[s] + 256) : 0.0f;
        }
    }

    // ---- 2 independent compute + store chains ----
    #pragma unroll
    for (int s = 0; s < NSTREAMS; s++) {
        const float4 a = va[s], b = vb[s];
        float4 oa, ob;
        oa.x = fmaf(w0[s], lA[s], fmaf(w1[s], a.x, fmaf(w2[s], a.y, bv[s])));
        oa.y = fmaf(w0[s], a.x, fmaf(w1[s], a.y, fmaf(w2[s], a.z, bv[s])));
        oa.z = fmaf(w0[s], a.y, fmaf(w1[s], a.z, fmaf(w2[s], a.w, bv[s])));
        oa.w = fmaf(w0[s], a.z, fmaf(w1[s], a.w, fmaf(w2[s], rA[s], bv[s])));

        ob.x = fmaf(w0[s], lB[s], fmaf(w1[s], b.x, fmaf(w2[s], b.y, bv[s])));
        ob.y = fmaf(w0[s], b.x, fmaf(w1[s], b.y, fmaf(w2[s], b.z, bv[s])));
        ob.z = fmaf(w0[s], b.y, fmaf(w1[s], b.z, fmaf(w2[s], b.w, bv[s])));
        ob.w = fmaf(w0[s], b.z, fmaf(w1[s], b.w, fmaf(w2[s], rB[s], bv[s])));

        float4* ov = reinterpret_cast<float4*>(out + Wb[s]);
        __stcs(&ov[lane],      oa);   // dense 512B warp store
        __stcs(&ov[lane + 32], ob);   // dense 512B warp store
    }
}

extern "C" void kernel_launch(void* const* d_in, const int* in_sizes, int n_in,
                              void* d_out, int out_size)
{
    const float* x    = (const float*)d_in[0];
    const float* w    = (const float*)d_in[1];
    const float* bias = (const float*)d_in[2];
    float*       out  = (float*)d_out;

    // each warp covers 256 elems per stream, 2 streams -> 512 elems/warp
    const int threads = 256;                                   // 8 warps/CTA
    const int blocks  = HALF_ELEMS / (256 * 8);                // 16384

    dwconv1d_k3_kernel<<<blocks, threads>>>(x, w, bias, out);
}